// round 2
// baseline (speedup 1.0000x reference)
#include <cuda_runtime.h>
#include <cuda_bf16.h>
#include <cstdint>

// Problem dims
#define BN 16
#define CH 64
#define HH 256
#define WW 256
#define HW (HH*WW)           // 65536
#define M_PER_CH (BN*HW)     // 1048576

// Scratch: conv output (bias omitted — it cancels in BN), stats
__device__ float g_conv[(size_t)BN*CH*HH*WW];   // 256 MB
__device__ float g_psum[CH*32];
__device__ float g_psq[CH*32];
__device__ float g_scale[CH];
__device__ float g_shift[CH];

// ---------------------------------------------------------------------------
// Kernel 1: direct dilated conv (k=3, dil=2, pad=2), no bias.
// Block tile: CO_T=16, H_T=16, W_T=32 (8192 outputs). 256 threads,
// each thread: 8 co x 4 w x 1 h  (32 accumulators).
// ---------------------------------------------------------------------------
__global__ __launch_bounds__(256) void conv_kernel(const float* __restrict__ x,
                                                   const float* __restrict__ wgt)
{
    __shared__ float sw[16*64*9];   // 36 KB: all weights for this co-group
    __shared__ float sx[20*37];     // padded x tile, conflict-free stride 37

    const int t  = threadIdx.x;
    const int wt = blockIdx.x;            // 0..7
    const int ht = blockIdx.y;            // 0..15
    const int nz = blockIdx.z;            // 0..63
    const int n   = nz >> 2;
    const int cog = nz & 3;
    const int w0 = wt * 32;
    const int h0 = ht * 16;

    const int wq = t & 7;          // w quad (4 px each)
    const int hq = (t >> 3) & 15;  // row within tile
    const int cq = t >> 7;         // co half (0/1)

    // Stage all 16co x 64ci x 9 weights once
    for (int idx = t; idx < 16*64*9; idx += 256)
        sw[idx] = wgt[cog*16*64*9 + idx];

    float acc[8][4];
    #pragma unroll
    for (int u = 0; u < 8; u++)
        #pragma unroll
        for (int j = 0; j < 4; j++) acc[u][j] = 0.f;

    const float* xn = x + (size_t)n * CH * HW;

    for (int ci = 0; ci < CH; ci++) {
        __syncthreads();   // protect sx from previous iteration's readers
        const float* xp = xn + ci * HW;
        // load 20x36 input tile (rows h0-2..h0+17, cols w0-2..w0+33)
        for (int idx = t; idx < 20*36; idx += 256) {
            int r = idx / 36, c = idx % 36;
            int gh = h0 + r - 2, gw = w0 + c - 2;
            float v = 0.f;
            if ((unsigned)gh < 256u && (unsigned)gw < 256u)
                v = xp[gh*WW + gw];
            sx[r*37 + c] = v;
        }
        __syncthreads();   // also covers the one-time weight staging

        // gather the 3x8 input window this thread needs
        float xv[3][8];
        #pragma unroll
        for (int rr = 0; rr < 3; rr++)
            #pragma unroll
            for (int cc = 0; cc < 8; cc++)
                xv[rr][cc] = sx[(hq + rr*2)*37 + wq*4 + cc];

        #pragma unroll
        for (int u = 0; u < 8; u++) {
            const float* wp = &sw[((cq*8 + u)*64 + ci)*9];
            float wr[9];
            #pragma unroll
            for (int k = 0; k < 9; k++) wr[k] = wp[k];
            #pragma unroll
            for (int kh = 0; kh < 3; kh++)
                #pragma unroll
                for (int kw = 0; kw < 3; kw++)
                    #pragma unroll
                    for (int j = 0; j < 4; j++)
                        acc[u][j] = fmaf(xv[kh][j + 2*kw], wr[kh*3 + kw], acc[u][j]);
        }
    }

    const int h = h0 + hq;
    const int w = w0 + wq*4;
    #pragma unroll
    for (int u = 0; u < 8; u++) {
        int co = cog*16 + cq*8 + u;
        size_t off = (((size_t)(n*CH + co)) << 16) + h*WW + w;
        *(float4*)&g_conv[off] = make_float4(acc[u][0], acc[u][1], acc[u][2], acc[u][3]);
    }
}

// ---------------------------------------------------------------------------
// Kernel 2a: per-channel partial sum / sumsq (deterministic tree reduction)
// grid (32, 64): block b handles half of one n-plane of channel c.
// ---------------------------------------------------------------------------
__global__ __launch_bounds__(256) void stats_kernel()
{
    const int c = blockIdx.y;
    const int b = blockIdx.x;             // 0..31
    const int t = threadIdx.x;
    const int n = b >> 1;
    const int half = b & 1;

    const float4* p = (const float4*)(g_conv + (((size_t)(n*CH + c)) << 16) + (half << 15));
    float s = 0.f, q = 0.f;
    #pragma unroll 8
    for (int i = 0; i < 32; i++) {
        float4 v = p[t + i*256];
        s += v.x + v.y + v.z + v.w;
        q += v.x*v.x + v.y*v.y + v.z*v.z + v.w*v.w;
    }
    __shared__ float ss[256], sq[256];
    ss[t] = s; sq[t] = q;
    __syncthreads();
    for (int st = 128; st > 0; st >>= 1) {
        if (t < st) { ss[t] += ss[t+st]; sq[t] += sq[t+st]; }
        __syncthreads();
    }
    if (t == 0) { g_psum[c*32 + b] = ss[0]; g_psq[c*32 + b] = sq[0]; }
}

// ---------------------------------------------------------------------------
// Kernel 2b: finalize mean/var -> scale/shift  (bias cancels; not needed)
// ---------------------------------------------------------------------------
__global__ void finalize_stats(const float* __restrict__ gamma,
                               const float* __restrict__ beta)
{
    int c = threadIdx.x;   // 64 threads
    float s = 0.f, q = 0.f;
    for (int b = 0; b < 32; b++) { s += g_psum[c*32 + b]; q += g_psq[c*32 + b]; }
    const float invM = 1.f / (float)M_PER_CH;
    float m   = s * invM;
    float var = q * invM - m*m;
    float inv = rsqrtf(var + 1e-5f);
    float sc  = gamma[c] * inv;
    g_scale[c] = sc;
    g_shift[c] = beta[c] - sc * m;
}

// ---------------------------------------------------------------------------
// Kernel 3: normalize + ReLU + 4x4 block bitonic sort; write [a | y]
// One thread per 4x4 spatial block.
// ---------------------------------------------------------------------------
__global__ __launch_bounds__(256) void bn_sort_kernel(float* __restrict__ out)
{
    int tid = blockIdx.x * 256 + threadIdx.x;      // 0 .. 4194303
    int bw = tid & 63;
    int bh = (tid >> 6) & 63;
    int c  = (tid >> 12) & 63;
    int n  = tid >> 18;

    float sc = g_scale[c];
    float sh = g_shift[c];

    size_t ibase = ((((size_t)(n*CH + c)) << 8) + bh*4) * WW + bw*4;
    float v[16];
    #pragma unroll
    for (int r = 0; r < 4; r++) {
        float4 q = *(const float4*)&g_conv[ibase + (size_t)r*WW];
        v[r*4+0] = fmaxf(fmaf(q.x, sc, sh), 0.f);
        v[r*4+1] = fmaxf(fmaf(q.y, sc, sh), 0.f);
        v[r*4+2] = fmaxf(fmaf(q.z, sc, sh), 0.f);
        v[r*4+3] = fmaxf(fmaf(q.w, sc, sh), 0.f);
    }

    size_t obase = ((((size_t)(n*128 + c)) << 8) + bh*4) * WW + bw*4;
    #pragma unroll
    for (int r = 0; r < 4; r++)
        *(float4*)&out[obase + (size_t)r*WW] =
            make_float4(v[r*4+0], v[r*4+1], v[r*4+2], v[r*4+3]);

    // bitonic sort 16 (ascending), fully unrolled -> min/max network
    #pragma unroll
    for (int k = 2; k <= 16; k <<= 1) {
        #pragma unroll
        for (int j = k >> 1; j > 0; j >>= 1) {
            #pragma unroll
            for (int i = 0; i < 16; i++) {
                int ix = i ^ j;
                if (ix > i) {
                    float a = v[i], b = v[ix];
                    float lo = fminf(a, b), hi = fmaxf(a, b);
                    bool up = ((i & k) == 0);
                    v[i]  = up ? lo : hi;
                    v[ix] = up ? hi : lo;
                }
            }
        }
    }

    size_t ybase = obase + ((size_t)64 << 16);   // channel c+64
    #pragma unroll
    for (int r = 0; r < 4; r++)
        *(float4*)&out[ybase + (size_t)r*WW] =
            make_float4(v[r*4+0], v[r*4+1], v[r*4+2], v[r*4+3]);
}

// ---------------------------------------------------------------------------
extern "C" void kernel_launch(void* const* d_in, const int* in_sizes, int n_in,
                              void* d_out, int out_size)
{
    const float* x     = (const float*)d_in[0];
    const float* wgt   = (const float*)d_in[1];
    // d_in[2] = conv_b : mathematically cancelled by training-mode BN
    const float* gamma = (const float*)d_in[3];
    const float* beta  = (const float*)d_in[4];
    float* out = (float*)d_out;

    conv_kernel<<<dim3(8, 16, 64), 256>>>(x, wgt);
    stats_kernel<<<dim3(32, 64), 256>>>();
    finalize_stats<<<1, 64>>>(gamma, beta);
    bn_sort_kernel<<<16384, 256>>>(out);
}

// round 3
// speedup vs baseline: 1.0014x; 1.0014x over previous
#include <cuda_runtime.h>
#include <cuda_bf16.h>
#include <cstdint>

// Problem dims
#define BN 16
#define CH 64
#define HH 256
#define WW 256
#define HW (HH*WW)           // 65536
#define M_PER_CH (BN*HW)     // 1048576

// Scratch: conv output (bias omitted — it cancels in BN), stats
__device__ float g_conv[(size_t)BN*CH*HH*WW];   // 256 MB
__device__ float g_psum[CH*32];
__device__ float g_psq[CH*32];
__device__ float g_scale[CH];
__device__ float g_shift[CH];

// ---------------------------------------------------------------------------
// Kernel 1: direct dilated conv (k=3, dil=2, pad=2), no bias.
// Block tile: CO_T=16, H_T=16, W_T=32 (8192 outputs). 256 threads,
// each thread: 8 co x 4 w x 1 h  (32 accumulators).
// ---------------------------------------------------------------------------
__global__ __launch_bounds__(256) void conv_kernel(const float* __restrict__ x,
                                                   const float* __restrict__ wgt)
{
    __shared__ float sw[16*64*9];   // 36 KB: all weights for this co-group
    __shared__ float sx[20*37];     // padded x tile, conflict-free stride 37

    const int t  = threadIdx.x;
    const int wt = blockIdx.x;            // 0..7
    const int ht = blockIdx.y;            // 0..15
    const int nz = blockIdx.z;            // 0..63
    const int n   = nz >> 2;
    const int cog = nz & 3;
    const int w0 = wt * 32;
    const int h0 = ht * 16;

    const int wq = t & 7;          // w quad (4 px each)
    const int hq = (t >> 3) & 15;  // row within tile
    const int cq = t >> 7;         // co half (0/1)

    // Stage all 16co x 64ci x 9 weights once
    for (int idx = t; idx < 16*64*9; idx += 256)
        sw[idx] = wgt[cog*16*64*9 + idx];

    float acc[8][4];
    #pragma unroll
    for (int u = 0; u < 8; u++)
        #pragma unroll
        for (int j = 0; j < 4; j++) acc[u][j] = 0.f;

    const float* xn = x + (size_t)n * CH * HW;

    for (int ci = 0; ci < CH; ci++) {
        __syncthreads();   // protect sx from previous iteration's readers
        const float* xp = xn + ci * HW;
        // load 20x36 input tile (rows h0-2..h0+17, cols w0-2..w0+33)
        for (int idx = t; idx < 20*36; idx += 256) {
            int r = idx / 36, c = idx % 36;
            int gh = h0 + r - 2, gw = w0 + c - 2;
            float v = 0.f;
            if ((unsigned)gh < 256u && (unsigned)gw < 256u)
                v = xp[gh*WW + gw];
            sx[r*37 + c] = v;
        }
        __syncthreads();   // also covers the one-time weight staging

        // gather the 3x8 input window this thread needs
        float xv[3][8];
        #pragma unroll
        for (int rr = 0; rr < 3; rr++)
            #pragma unroll
            for (int cc = 0; cc < 8; cc++)
                xv[rr][cc] = sx[(hq + rr*2)*37 + wq*4 + cc];

        #pragma unroll
        for (int u = 0; u < 8; u++) {
            const float* wp = &sw[((cq*8 + u)*64 + ci)*9];
            float wr[9];
            #pragma unroll
            for (int k = 0; k < 9; k++) wr[k] = wp[k];
            #pragma unroll
            for (int kh = 0; kh < 3; kh++)
                #pragma unroll
                for (int kw = 0; kw < 3; kw++)
                    #pragma unroll
                    for (int j = 0; j < 4; j++)
                        acc[u][j] = fmaf(xv[kh][j + 2*kw], wr[kh*3 + kw], acc[u][j]);
        }
    }

    const int h = h0 + hq;
    const int w = w0 + wq*4;
    #pragma unroll
    for (int u = 0; u < 8; u++) {
        int co = cog*16 + cq*8 + u;
        size_t off = (((size_t)(n*CH + co)) << 16) + h*WW + w;
        *(float4*)&g_conv[off] = make_float4(acc[u][0], acc[u][1], acc[u][2], acc[u][3]);
    }
}

// ---------------------------------------------------------------------------
// Kernel 2a: per-channel partial sum / sumsq (deterministic tree reduction)
// grid (32, 64): block b handles half of one n-plane of channel c.
// ---------------------------------------------------------------------------
__global__ __launch_bounds__(256) void stats_kernel()
{
    const int c = blockIdx.y;
    const int b = blockIdx.x;             // 0..31
    const int t = threadIdx.x;
    const int n = b >> 1;
    const int half = b & 1;

    const float4* p = (const float4*)(g_conv + (((size_t)(n*CH + c)) << 16) + (half << 15));
    float s = 0.f, q = 0.f;
    #pragma unroll 8
    for (int i = 0; i < 32; i++) {
        float4 v = p[t + i*256];
        s += v.x + v.y + v.z + v.w;
        q += v.x*v.x + v.y*v.y + v.z*v.z + v.w*v.w;
    }
    __shared__ float ss[256], sq[256];
    ss[t] = s; sq[t] = q;
    __syncthreads();
    for (int st = 128; st > 0; st >>= 1) {
        if (t < st) { ss[t] += ss[t+st]; sq[t] += sq[t+st]; }
        __syncthreads();
    }
    if (t == 0) { g_psum[c*32 + b] = ss[0]; g_psq[c*32 + b] = sq[0]; }
}

// ---------------------------------------------------------------------------
// Kernel 2b: finalize mean/var -> scale/shift  (bias cancels; not needed)
// ---------------------------------------------------------------------------
__global__ void finalize_stats(const float* __restrict__ gamma,
                               const float* __restrict__ beta)
{
    int c = threadIdx.x;   // 64 threads
    float s = 0.f, q = 0.f;
    for (int b = 0; b < 32; b++) { s += g_psum[c*32 + b]; q += g_psq[c*32 + b]; }
    const float invM = 1.f / (float)M_PER_CH;
    float m   = s * invM;
    float var = q * invM - m*m;
    float inv = rsqrtf(var + 1e-5f);
    float sc  = gamma[c] * inv;
    g_scale[c] = sc;
    g_shift[c] = beta[c] - sc * m;
}

// ---------------------------------------------------------------------------
// Kernel 3: normalize + ReLU + 4x4 block bitonic sort; write [a | y]
// One thread per 4x4 spatial block.
// ---------------------------------------------------------------------------
__global__ __launch_bounds__(256) void bn_sort_kernel(float* __restrict__ out)
{
    int tid = blockIdx.x * 256 + threadIdx.x;      // 0 .. 4194303
    int bw = tid & 63;
    int bh = (tid >> 6) & 63;
    int c  = (tid >> 12) & 63;
    int n  = tid >> 18;

    float sc = g_scale[c];
    float sh = g_shift[c];

    size_t ibase = ((((size_t)(n*CH + c)) << 8) + bh*4) * WW + bw*4;
    float v[16];
    #pragma unroll
    for (int r = 0; r < 4; r++) {
        float4 q = *(const float4*)&g_conv[ibase + (size_t)r*WW];
        v[r*4+0] = fmaxf(fmaf(q.x, sc, sh), 0.f);
        v[r*4+1] = fmaxf(fmaf(q.y, sc, sh), 0.f);
        v[r*4+2] = fmaxf(fmaf(q.z, sc, sh), 0.f);
        v[r*4+3] = fmaxf(fmaf(q.w, sc, sh), 0.f);
    }

    size_t obase = ((((size_t)(n*128 + c)) << 8) + bh*4) * WW + bw*4;
    #pragma unroll
    for (int r = 0; r < 4; r++)
        *(float4*)&out[obase + (size_t)r*WW] =
            make_float4(v[r*4+0], v[r*4+1], v[r*4+2], v[r*4+3]);

    // bitonic sort 16 (ascending), fully unrolled -> min/max network
    #pragma unroll
    for (int k = 2; k <= 16; k <<= 1) {
        #pragma unroll
        for (int j = k >> 1; j > 0; j >>= 1) {
            #pragma unroll
            for (int i = 0; i < 16; i++) {
                int ix = i ^ j;
                if (ix > i) {
                    float a = v[i], b = v[ix];
                    float lo = fminf(a, b), hi = fmaxf(a, b);
                    bool up = ((i & k) == 0);
                    v[i]  = up ? lo : hi;
                    v[ix] = up ? hi : lo;
                }
            }
        }
    }

    size_t ybase = obase + ((size_t)64 << 16);   // channel c+64
    #pragma unroll
    for (int r = 0; r < 4; r++)
        *(float4*)&out[ybase + (size_t)r*WW] =
            make_float4(v[r*4+0], v[r*4+1], v[r*4+2], v[r*4+3]);
}

// ---------------------------------------------------------------------------
extern "C" void kernel_launch(void* const* d_in, const int* in_sizes, int n_in,
                              void* d_out, int out_size)
{
    const float* x     = (const float*)d_in[0];
    const float* wgt   = (const float*)d_in[1];
    // d_in[2] = conv_b : mathematically cancelled by training-mode BN
    const float* gamma = (const float*)d_in[3];
    const float* beta  = (const float*)d_in[4];
    float* out = (float*)d_out;

    conv_kernel<<<dim3(8, 16, 64), 256>>>(x, wgt);
    stats_kernel<<<dim3(32, 64), 256>>>();
    finalize_stats<<<1, 64>>>(gamma, beta);
    bn_sort_kernel<<<16384, 256>>>(out);
}

// round 5
// speedup vs baseline: 4.0595x; 4.0539x over previous
#include <cuda_runtime.h>
#include <cuda_fp16.h>
#include <cstdint>

#define HW 65536
#define M_PER_CH (16*HW)

__device__ float g_conv[(size_t)16*64*HW];     // 256 MB scratch
__device__ float g_psum[64*148];
__device__ float g_psq[64*148];
__device__ float g_scale[64];
__device__ float g_shift[64];

// SMEM layout (dynamic):
//   W tiles : [0, 82944)           9 taps x [64 co][72 halves] (stride 144B)
//   A tile  : [82944, +19008)      [132 px][72 halves] (stride 144B)
//   sbuf    : [82944, +33792)      epilogue float[128][66]  (overlaps A)
#define WOFF 0
#define AOFF 82944
#define SMEM_REQ (82944 + 33792)
#define WTAP 9216      // 64*144

__device__ __forceinline__ uint32_t s2u(const void* p) {
    uint32_t a;
    asm("{ .reg .u64 t; cvta.to.shared.u64 t, %1; cvt.u32.u64 %0, t; }" : "=r"(a) : "l"(p));
    return a;
}
__device__ __forceinline__ void ldsm4(uint32_t& r0, uint32_t& r1, uint32_t& r2, uint32_t& r3,
                                      uint32_t addr) {
    asm volatile("ldmatrix.sync.aligned.m8n8.x4.shared.b16 {%0,%1,%2,%3}, [%4];"
                 : "=r"(r0), "=r"(r1), "=r"(r2), "=r"(r3) : "r"(addr));
}
__device__ __forceinline__ void mma16816(float* c, uint32_t a0, uint32_t a1, uint32_t a2,
                                         uint32_t a3, uint32_t b0, uint32_t b1) {
    asm volatile("mma.sync.aligned.m16n8k16.row.col.f32.f16.f16.f32 "
                 "{%0,%1,%2,%3}, {%4,%5,%6,%7}, {%8,%9}, {%0,%1,%2,%3};"
                 : "+f"(c[0]), "+f"(c[1]), "+f"(c[2]), "+f"(c[3])
                 : "r"(a0), "r"(a1), "r"(a2), "r"(a3), "r"(b0), "r"(b1));
}
__device__ __forceinline__ uint32_t packh2(float a, float b) {
    __half2 h = __floats2half2_rn(a, b);
    return *(uint32_t*)&h;
}

// Load one kh-row of x into registers (8448 halves as 256x uint4 + 32 edge uint4)
__device__ __forceinline__ void stage_load(const float* __restrict__ x, int n, int hrow,
                                           int w0, bool valid, int t, uint4 pk[4], uint4& pke)
{
    const bool rowok = valid && ((unsigned)hrow < 256u);
    const int px   = t & 127;
    const int octh = t >> 7;
    const int wg   = w0 - 2 + px;
    const bool wok = rowok && ((unsigned)wg < 256u);
    const size_t rb = (size_t)(hrow*256 + wg);   // only used when wok

    #pragma unroll
    for (int r = 0; r < 4; r++) {
        const int oct = 2*r + octh;
        const size_t base = (((size_t)(n*64 + oct*8)) << 16) + rb;
        float v[8];
        #pragma unroll
        for (int i = 0; i < 8; i++)
            v[i] = wok ? __ldg(&x[base + ((size_t)i << 16)]) : 0.f;
        pk[r].x = packh2(v[0], v[1]);
        pk[r].y = packh2(v[2], v[3]);
        pk[r].z = packh2(v[4], v[5]);
        pk[r].w = packh2(v[6], v[7]);
    }
    pke = make_uint4(0, 0, 0, 0);
    if (t < 32) {
        const int pxe = 128 + (t & 3);
        const int oct = t >> 2;
        const int we = w0 - 2 + pxe;
        const bool ewok = rowok && ((unsigned)we < 256u);
        const size_t base = (((size_t)(n*64 + oct*8)) << 16) + (size_t)(hrow*256 + we);
        float v[8];
        #pragma unroll
        for (int i = 0; i < 8; i++)
            v[i] = ewok ? __ldg(&x[base + ((size_t)i << 16)]) : 0.f;
        pke.x = packh2(v[0], v[1]);
        pke.y = packh2(v[2], v[3]);
        pke.z = packh2(v[4], v[5]);
        pke.w = packh2(v[6], v[7]);
    }
}

// ---------------------------------------------------------------------------
// HMMA implicit-GEMM dilated conv (k=3, dil=2, pad=2) + fused channel stats.
// Persistent 148 CTAs; tile = (n, h, w-half): 128 px x 64 co.
// ---------------------------------------------------------------------------
__global__ __launch_bounds__(256, 1)
void conv_tc(const float* __restrict__ x, const float* __restrict__ wgt)
{
    extern __shared__ char sm[];
    const int t  = threadIdx.x;
    const int L  = t & 31;
    const int wi = t >> 5;
    const int Pm = (wi >> 1) * 32;
    const int Nb = (wi & 1) * 32;

    // ---- stage weights: [tap][co][ci] fp16, row stride 144B ----
    {
        const int co = t & 63;
        const int o0 = t >> 6;   // 0..3
        for (int r = 0; r < 2; r++) {
            const int oct = o0 + 4*r;
            for (int tap = 0; tap < 9; tap++) {
                float v[8];
                #pragma unroll
                for (int i = 0; i < 8; i++)
                    v[i] = __ldg(&wgt[co*576 + (oct*8 + i)*9 + tap]);
                uint4 p;
                p.x = packh2(v[0], v[1]); p.y = packh2(v[2], v[3]);
                p.z = packh2(v[4], v[5]); p.w = packh2(v[6], v[7]);
                *(uint4*)(sm + WOFF + tap*WTAP + co*144 + oct*16) = p;
            }
        }
    }
    __syncthreads();

    const uint32_t Ab = s2u(sm + AOFF);
    const uint32_t Wb = s2u(sm + WOFF);
    float* sbuf = (float*)(sm + AOFF);

    // lane-constant ldmatrix bases
    uint32_t aconst[2];
    #pragma unroll
    for (int mi = 0; mi < 2; mi++)
        aconst[mi] = Ab + (uint32_t)((Pm + mi*16 + (L & 15)) * 144 + ((L >> 4) * 16));
    const uint32_t bconst = Wb + (uint32_t)((Nb + ((L >> 3) & 3)*8 + (L & 7)) * 144);

    float accS[8], accQ[8];
    #pragma unroll
    for (int i = 0; i < 8; i++) { accS[i] = 0.f; accQ[i] = 0.f; }

    const int t0 = (blockIdx.x * 8192) / 148;
    const int t1 = ((blockIdx.x + 1) * 8192) / 148;

    uint4 pk[4], pke;
    if (t0 < t1) {
        const int wc = t0 & 1, h = (t0 >> 1) & 255, n = t0 >> 9;
        stage_load(x, n, h - 2, wc << 7, true, t, pk, pke);
    }

    for (int tile = t0; tile < t1; tile++) {
        const int wc = tile & 1, h = (tile >> 1) & 255, n = tile >> 9;
        const int w0 = wc << 7;

        float c[32];
        #pragma unroll
        for (int i = 0; i < 32; i++) c[i] = 0.f;

        for (int kh = 0; kh < 3; kh++) {
            __syncthreads();                       // A free for overwrite
            // store staged row
            {
                const int px = t & 127, octh = t >> 7;
                #pragma unroll
                for (int r = 0; r < 4; r++)
                    *(uint4*)(sm + AOFF + px*144 + (2*r + octh)*16) = pk[r];
                if (t < 32)
                    *(uint4*)(sm + AOFF + (128 + (t & 3))*144 + (t >> 2)*16) = pke;
            }
            __syncthreads();

            // prefetch next stage (hidden under the MMA loop below)
            if (kh < 2) {
                stage_load(x, n, h + 2*(kh + 1) - 2, w0, true, t, pk, pke);
            } else {
                const int nt = tile + 1;
                const bool v = nt < t1;
                const int wc2 = nt & 1, h2 = (nt >> 1) & 255, n2 = nt >> 9;
                stage_load(x, v ? n2 : 0, h2 - 2, wc2 << 7, v, t, pk, pke);
            }

            // 3 kw taps x 4 k16-steps
            #pragma unroll
            for (int kw = 0; kw < 3; kw++) {
                #pragma unroll
                for (int ks = 0; ks < 4; ks++) {
                    const uint32_t aoff = (uint32_t)(kw*288 + ks*32);
                    uint32_t A0[4], A1[4], B0[4], B1[4];
                    ldsm4(A0[0], A0[1], A0[2], A0[3], aconst[0] + aoff);
                    ldsm4(A1[0], A1[1], A1[2], A1[3], aconst[1] + aoff);
                    const uint32_t boff = (uint32_t)((kh*3 + kw)*WTAP + ks*32);
                    ldsm4(B0[0], B0[1], B0[2], B0[3], bconst + boff);
                    ldsm4(B1[0], B1[1], B1[2], B1[3], bconst + boff + 16);
                    #pragma unroll
                    for (int nj = 0; nj < 4; nj++) {
                        mma16816(&c[nj*4],      A0[0], A0[1], A0[2], A0[3], B0[nj], B1[nj]);
                        mma16816(&c[16 + nj*4], A1[0], A1[1], A1[2], A1[3], B0[nj], B1[nj]);
                    }
                }
            }
        }

        // ---- epilogue: frags -> sbuf -> g_conv (+stats) ----
        __syncthreads();              // all warps done reading A (sbuf overlaps)
        #pragma unroll
        for (int mi = 0; mi < 2; mi++) {
            #pragma unroll
            for (int nj = 0; nj < 4; nj++) {
                const float* cf = &c[mi*16 + nj*4];
                const int px0 = Pm + mi*16 + (L >> 2);
                const int co  = Nb + nj*8 + 2*(L & 3);
                *(float2*)(sbuf + px0*66 + co)       = make_float2(cf[0], cf[1]);
                *(float2*)(sbuf + (px0 + 8)*66 + co) = make_float2(cf[2], cf[3]);
            }
        }
        __syncthreads();

        const int co0 = wi * 8;
        #pragma unroll
        for (int i = 0; i < 8; i++) {
            const int co = co0 + i;
            const size_t gb = (((size_t)(n*64 + co)) << 16) + (size_t)h*256 + w0;
            #pragma unroll
            for (int j = 0; j < 4; j++) {
                const int px = L + 32*j;
                float v = sbuf[px*66 + co];
                accS[i] += v; accQ[i] += v*v;
                g_conv[gb + px] = v;
            }
        }
    }

    // ---- per-CTA stats writeout (warp wi owns co wi*8 .. wi*8+7) ----
    #pragma unroll
    for (int i = 0; i < 8; i++) {
        float s = accS[i], q = accQ[i];
        #pragma unroll
        for (int off = 16; off > 0; off >>= 1) {
            s += __shfl_xor_sync(0xffffffffu, s, off);
            q += __shfl_xor_sync(0xffffffffu, q, off);
        }
        if (L == 0) {
            g_psum[(wi*8 + i)*148 + blockIdx.x] = s;
            g_psq [(wi*8 + i)*148 + blockIdx.x] = q;
        }
    }
}

// ---------------------------------------------------------------------------
__global__ void finalize_stats(const float* __restrict__ gamma,
                               const float* __restrict__ beta)
{
    int c = threadIdx.x;   // 64 threads
    float s = 0.f, q = 0.f;
    for (int b = 0; b < 148; b++) { s += g_psum[c*148 + b]; q += g_psq[c*148 + b]; }
    const float invM = 1.f / (float)M_PER_CH;
    float m   = s * invM;
    float var = q * invM - m*m;
    float inv = rsqrtf(var + 1e-5f);
    float sc  = gamma[c] * inv;
    g_scale[c] = sc;
    g_shift[c] = beta[c] - sc * m;
}

// ---------------------------------------------------------------------------
// normalize + ReLU + 4x4 block bitonic sort; write [a | y]  (DRAM roofline)
// ---------------------------------------------------------------------------
__global__ __launch_bounds__(256) void bn_sort_kernel(float* __restrict__ out)
{
    int tid = blockIdx.x * 256 + threadIdx.x;
    int bw = tid & 63, bh = (tid >> 6) & 63, c = (tid >> 12) & 63, n = tid >> 18;
    float sc = g_scale[c], sh = g_shift[c];

    size_t ibase = ((((size_t)(n*64 + c)) << 8) + bh*4) * 256 + bw*4;
    float v[16];
    #pragma unroll
    for (int r = 0; r < 4; r++) {
        float4 q = *(const float4*)&g_conv[ibase + (size_t)r*256];
        v[r*4+0] = fmaxf(fmaf(q.x, sc, sh), 0.f);
        v[r*4+1] = fmaxf(fmaf(q.y, sc, sh), 0.f);
        v[r*4+2] = fmaxf(fmaf(q.z, sc, sh), 0.f);
        v[r*4+3] = fmaxf(fmaf(q.w, sc, sh), 0.f);
    }
    size_t obase = ((((size_t)(n*128 + c)) << 8) + bh*4) * 256 + bw*4;
    #pragma unroll
    for (int r = 0; r < 4; r++)
        *(float4*)&out[obase + (size_t)r*256] =
            make_float4(v[r*4+0], v[r*4+1], v[r*4+2], v[r*4+3]);

    #pragma unroll
    for (int k = 2; k <= 16; k <<= 1)
        #pragma unroll
        for (int j = k >> 1; j > 0; j >>= 1)
            #pragma unroll
            for (int i = 0; i < 16; i++) {
                int ix = i ^ j;
                if (ix > i) {
                    float a = v[i], b = v[ix];
                    float lo = fminf(a, b), hi = fmaxf(a, b);
                    bool up = ((i & k) == 0);
                    v[i] = up ? lo : hi; v[ix] = up ? hi : lo;
                }
            }

    size_t ybase = obase + ((size_t)64 << 16);
    #pragma unroll
    for (int r = 0; r < 4; r++)
        *(float4*)&out[ybase + (size_t)r*256] =
            make_float4(v[r*4+0], v[r*4+1], v[r*4+2], v[r*4+3]);
}

// ---------------------------------------------------------------------------
extern "C" void kernel_launch(void* const* d_in, const int* in_sizes, int n_in,
                              void* d_out, int out_size)
{
    const float* x     = (const float*)d_in[0];
    const float* wgt   = (const float*)d_in[1];
    // d_in[2] = conv_b : cancels exactly in training-mode BN
    const float* gamma = (const float*)d_in[3];
    const float* beta  = (const float*)d_in[4];
    float* out = (float*)d_out;

    cudaFuncSetAttribute(conv_tc, cudaFuncAttributeMaxDynamicSharedMemorySize, SMEM_REQ);
    conv_tc<<<148, 256, SMEM_REQ>>>(x, wgt);
    finalize_stats<<<1, 64>>>(gamma, beta);
    bn_sort_kernel<<<16384, 256>>>(out);
}

// round 6
// speedup vs baseline: 4.9896x; 1.2291x over previous
#include <cuda_runtime.h>
#include <cuda_fp16.h>
#include <cstdint>

#define HW 65536
#define M_PER_CH (16*HW)

__device__ float g_conv[(size_t)16*64*HW];     // 256 MB scratch
__device__ float g_psum[64*148];
__device__ float g_psq[64*148];
__device__ float g_scale[64];
__device__ float g_shift[64];

// SMEM layout (dynamic):
//   W tiles : [0, 82944)            9 taps x [64 co][72 halves] (stride 144B)
//   A ring  : [82944, +3*19008)     3 slots x [132 px][72 halves]
//   sbuf    : [139968, +33792)      epilogue float[128][66]
#define WOFF 0
#define AOFF 82944
#define ATILE 19008
#define SBOFF 139968
#define SMEM_REQ (139968 + 33792)
#define WTAP 9216      // 64*144

__device__ __forceinline__ uint32_t s2u(const void* p) {
    uint32_t a;
    asm("{ .reg .u64 t; cvta.to.shared.u64 t, %1; cvt.u32.u64 %0, t; }" : "=r"(a) : "l"(p));
    return a;
}
__device__ __forceinline__ void ldsm4(uint32_t& r0, uint32_t& r1, uint32_t& r2, uint32_t& r3,
                                      uint32_t addr) {
    asm volatile("ldmatrix.sync.aligned.m8n8.x4.shared.b16 {%0,%1,%2,%3}, [%4];"
                 : "=r"(r0), "=r"(r1), "=r"(r2), "=r"(r3) : "r"(addr));
}
__device__ __forceinline__ void mma16816(float* c, uint32_t a0, uint32_t a1, uint32_t a2,
                                         uint32_t a3, uint32_t b0, uint32_t b1) {
    asm volatile("mma.sync.aligned.m16n8k16.row.col.f32.f16.f16.f32 "
                 "{%0,%1,%2,%3}, {%4,%5,%6,%7}, {%8,%9}, {%0,%1,%2,%3};"
                 : "+f"(c[0]), "+f"(c[1]), "+f"(c[2]), "+f"(c[3])
                 : "r"(a0), "r"(a1), "r"(a2), "r"(a3), "r"(b0), "r"(b1));
}
__device__ __forceinline__ uint32_t packh2(float a, float b) {
    __half2 h = __floats2half2_rn(a, b);
    return *(uint32_t*)&h;
}

// Load one x row (132 px x 64 ci) into regs: 128px x 8ci per r-iter + 4-edge
__device__ __forceinline__ void stage_load(const float* __restrict__ x, int n, int hrow,
                                           int w0, bool valid, int t, uint4 pk[4], uint4& pke)
{
    const bool rowok = valid && ((unsigned)hrow < 256u);
    const int px   = t & 127;
    const int octh = t >> 7;
    const int wg   = w0 - 2 + px;
    const bool wok = rowok && ((unsigned)wg < 256u);
    const size_t rb = (size_t)(hrow*256 + wg);

    #pragma unroll
    for (int r = 0; r < 4; r++) {
        const int oct = 2*r + octh;
        const size_t base = (((size_t)(n*64 + oct*8)) << 16) + rb;
        float v[8];
        #pragma unroll
        for (int i = 0; i < 8; i++)
            v[i] = wok ? __ldg(&x[base + ((size_t)i << 16)]) : 0.f;
        pk[r].x = packh2(v[0], v[1]);
        pk[r].y = packh2(v[2], v[3]);
        pk[r].z = packh2(v[4], v[5]);
        pk[r].w = packh2(v[6], v[7]);
    }
    pke = make_uint4(0, 0, 0, 0);
    if (t < 32) {
        const int pxe = 128 + (t & 3);
        const int oct = t >> 2;
        const int we = w0 - 2 + pxe;
        const bool ewok = rowok && ((unsigned)we < 256u);
        const size_t base = (((size_t)(n*64 + oct*8)) << 16) + (size_t)(hrow*256 + we);
        float v[8];
        #pragma unroll
        for (int i = 0; i < 8; i++)
            v[i] = ewok ? __ldg(&x[base + ((size_t)i << 16)]) : 0.f;
        pke.x = packh2(v[0], v[1]);
        pke.y = packh2(v[2], v[3]);
        pke.z = packh2(v[4], v[5]);
        pke.w = packh2(v[6], v[7]);
    }
}

__device__ __forceinline__ void stage_store(char* sm, int slot, int t,
                                            const uint4 pk[4], const uint4& pke)
{
    char* base = sm + AOFF + slot * ATILE;
    const int px = t & 127, octh = t >> 7;
    #pragma unroll
    for (int r = 0; r < 4; r++)
        *(uint4*)(base + px*144 + (2*r + octh)*16) = pk[r];
    if (t < 32)
        *(uint4*)(base + (128 + (t & 3))*144 + (t >> 2)*16) = pke;
}

// ---------------------------------------------------------------------------
// HMMA implicit-GEMM dilated conv + fused channel stats.
// Chain-major tile order: chain=(n,wc,parity), 128 tiles/chain stepping h+=2.
// 3-slot A row ring: steady state stages ONE new row per tile.
// ---------------------------------------------------------------------------
__global__ __launch_bounds__(256, 1)
void conv_tc(const float* __restrict__ x, const float* __restrict__ wgt)
{
    extern __shared__ char sm[];
    const int t  = threadIdx.x;
    const int L  = t & 31;
    const int wi = t >> 5;
    const int Pm = (wi >> 1) * 32;
    const int Nb = (wi & 1) * 32;

    // ---- stage weights: [tap][co][ci] fp16, row stride 144B ----
    {
        const int co = t & 63;
        const int o0 = t >> 6;   // 0..3
        for (int r = 0; r < 2; r++) {
            const int oct = o0 + 4*r;
            for (int tap = 0; tap < 9; tap++) {
                float v[8];
                #pragma unroll
                for (int i = 0; i < 8; i++)
                    v[i] = __ldg(&wgt[co*576 + (oct*8 + i)*9 + tap]);
                uint4 p;
                p.x = packh2(v[0], v[1]); p.y = packh2(v[2], v[3]);
                p.z = packh2(v[4], v[5]); p.w = packh2(v[6], v[7]);
                *(uint4*)(sm + WOFF + tap*WTAP + co*144 + oct*16) = p;
            }
        }
    }

    const uint32_t Ab = s2u(sm + AOFF);
    const uint32_t Wb = s2u(sm + WOFF);
    float* sbuf = (float*)(sm + SBOFF);

    // lane-constant offsets
    uint32_t aoffm[2];
    #pragma unroll
    for (int mi = 0; mi < 2; mi++)
        aoffm[mi] = (uint32_t)((Pm + mi*16 + (L & 15)) * 144 + ((L >> 4) * 16));
    const uint32_t bconst = Wb + (uint32_t)((Nb + ((L >> 3) & 3)*8 + (L & 7)) * 144);

    float accS[8], accQ[8];
    #pragma unroll
    for (int i = 0; i < 8; i++) { accS[i] = 0.f; accQ[i] = 0.f; }

    const int t0 = (blockIdx.x * 8192) / 148;
    const int t1 = ((blockIdx.x + 1) * 8192) / 148;

    uint4 pk[4], pke;
    int T = t0;

    __syncthreads();   // weights staged

    while (T < t1) {
        const int chain = T >> 7;
        int k = T & 127;
        const int n  = chain >> 2;
        const int wc = (chain >> 1) & 1;
        const int p  = chain & 1;
        int h = p + 2*k;
        const int w0 = wc << 7;
        const int seg_end = ((chain + 1) << 7) < t1 ? ((chain + 1) << 7) : t1;

        // prologue: rows h-2 -> slot k%3, h -> slot (k+1)%3
        stage_load(x, n, h - 2, w0, true, t, pk, pke);
        stage_store(sm, k % 3, t, pk, pke);
        stage_load(x, n, h, w0, true, t, pk, pke);
        stage_store(sm, (k + 1) % 3, t, pk, pke);
        stage_load(x, n, h + 2, w0, true, t, pk, pke);

        for (; T < seg_end; T++, k++, h += 2) {
            stage_store(sm, (k + 2) % 3, t, pk, pke);
            __syncthreads();

            // prefetch next row (hidden under MMAs)
            if (T + 1 < seg_end)
                stage_load(x, n, h + 4, w0, true, t, pk, pke);

            float c[32];
            #pragma unroll
            for (int i = 0; i < 32; i++) c[i] = 0.f;

            const int s0 = k % 3;
            #pragma unroll
            for (int kh = 0; kh < 3; kh++) {
                int sl = s0 + kh; if (sl >= 3) sl -= 3;
                const uint32_t abase = Ab + (uint32_t)sl * ATILE;
                #pragma unroll
                for (int kw = 0; kw < 3; kw++) {
                    #pragma unroll
                    for (int ks = 0; ks < 4; ks++) {
                        const uint32_t aoff = (uint32_t)(kw*288 + ks*32);
                        uint32_t A0[4], A1[4], B0[4], B1[4];
                        ldsm4(A0[0], A0[1], A0[2], A0[3], abase + aoffm[0] + aoff);
                        ldsm4(A1[0], A1[1], A1[2], A1[3], abase + aoffm[1] + aoff);
                        const uint32_t boff = (uint32_t)((kh*3 + kw)*WTAP + ks*32);
                        ldsm4(B0[0], B0[1], B0[2], B0[3], bconst + boff);
                        ldsm4(B1[0], B1[1], B1[2], B1[3], bconst + boff + 16);
                        #pragma unroll
                        for (int nj = 0; nj < 4; nj++) {
                            mma16816(&c[nj*4],      A0[0], A0[1], A0[2], A0[3], B0[nj], B1[nj]);
                            mma16816(&c[16 + nj*4], A1[0], A1[1], A1[2], A1[3], B0[nj], B1[nj]);
                        }
                    }
                }
            }

            // ---- epilogue: frags -> sbuf -> g_conv (+stats) ----
            #pragma unroll
            for (int mi = 0; mi < 2; mi++) {
                #pragma unroll
                for (int nj = 0; nj < 4; nj++) {
                    const float* cf = &c[mi*16 + nj*4];
                    const int px0 = Pm + mi*16 + (L >> 2);
                    const int co  = Nb + nj*8 + 2*(L & 3);
                    *(float2*)(sbuf + px0*66 + co)       = make_float2(cf[0], cf[1]);
                    *(float2*)(sbuf + (px0 + 8)*66 + co) = make_float2(cf[2], cf[3]);
                }
            }
            __syncthreads();

            const int co0 = wi * 8;
            #pragma unroll
            for (int i = 0; i < 8; i++) {
                const int co = co0 + i;
                const size_t gb = (((size_t)(n*64 + co)) << 16) + (size_t)h*256 + w0;
                #pragma unroll
                for (int j = 0; j < 4; j++) {
                    const int px = L + 32*j;
                    float v = sbuf[px*66 + co];
                    accS[i] += v; accQ[i] += v*v;
                    g_conv[gb + px] = v;
                }
            }
            __syncthreads();   // sbuf reads + A-slot ldsm reads done before next STS
        }
    }

    // ---- per-CTA stats writeout (warp wi owns co wi*8 .. wi*8+7) ----
    #pragma unroll
    for (int i = 0; i < 8; i++) {
        float s = accS[i], q = accQ[i];
        #pragma unroll
        for (int off = 16; off > 0; off >>= 1) {
            s += __shfl_xor_sync(0xffffffffu, s, off);
            q += __shfl_xor_sync(0xffffffffu, q, off);
        }
        if (L == 0) {
            g_psum[(wi*8 + i)*148 + blockIdx.x] = s;
            g_psq [(wi*8 + i)*148 + blockIdx.x] = q;
        }
    }
}

// ---------------------------------------------------------------------------
__global__ void finalize_stats(const float* __restrict__ gamma,
                               const float* __restrict__ beta)
{
    int c = threadIdx.x;   // 64 threads
    float s = 0.f, q = 0.f;
    for (int b = 0; b < 148; b++) { s += g_psum[c*148 + b]; q += g_psq[c*148 + b]; }
    const float invM = 1.f / (float)M_PER_CH;
    float m   = s * invM;
    float var = q * invM - m*m;
    float inv = rsqrtf(var + 1e-5f);
    float sc  = gamma[c] * inv;
    g_scale[c] = sc;
    g_shift[c] = beta[c] - sc * m;
}

// ---------------------------------------------------------------------------
// normalize + ReLU + 4x4 block bitonic sort; write [a | y]  (DRAM roofline)
// ---------------------------------------------------------------------------
__global__ __launch_bounds__(256) void bn_sort_kernel(float* __restrict__ out)
{
    int tid = blockIdx.x * 256 + threadIdx.x;
    int bw = tid & 63, bh = (tid >> 6) & 63, c = (tid >> 12) & 63, n = tid >> 18;
    float sc = g_scale[c], sh = g_shift[c];

    size_t ibase = ((((size_t)(n*64 + c)) << 8) + bh*4) * 256 + bw*4;
    float v[16];
    #pragma unroll
    for (int r = 0; r < 4; r++) {
        float4 q = *(const float4*)&g_conv[ibase + (size_t)r*256];
        v[r*4+0] = fmaxf(fmaf(q.x, sc, sh), 0.f);
        v[r*4+1] = fmaxf(fmaf(q.y, sc, sh), 0.f);
        v[r*4+2] = fmaxf(fmaf(q.z, sc, sh), 0.f);
        v[r*4+3] = fmaxf(fmaf(q.w, sc, sh), 0.f);
    }
    size_t obase = ((((size_t)(n*128 + c)) << 8) + bh*4) * 256 + bw*4;
    #pragma unroll
    for (int r = 0; r < 4; r++)
        *(float4*)&out[obase + (size_t)r*256] =
            make_float4(v[r*4+0], v[r*4+1], v[r*4+2], v[r*4+3]);

    #pragma unroll
    for (int k = 2; k <= 16; k <<= 1)
        #pragma unroll
        for (int j = k >> 1; j > 0; j >>= 1)
            #pragma unroll
            for (int i = 0; i < 16; i++) {
                int ix = i ^ j;
                if (ix > i) {
                    float a = v[i], b = v[ix];
                    float lo = fminf(a, b), hi = fmaxf(a, b);
                    bool up = ((i & k) == 0);
                    v[i] = up ? lo : hi; v[ix] = up ? hi : lo;
                }
            }

    size_t ybase = obase + ((size_t)64 << 16);
    #pragma unroll
    for (int r = 0; r < 4; r++)
        *(float4*)&out[ybase + (size_t)r*256] =
            make_float4(v[r*4+0], v[r*4+1], v[r*4+2], v[r*4+3]);
}

// ---------------------------------------------------------------------------
extern "C" void kernel_launch(void* const* d_in, const int* in_sizes, int n_in,
                              void* d_out, int out_size)
{
    const float* x     = (const float*)d_in[0];
    const float* wgt   = (const float*)d_in[1];
    // d_in[2] = conv_b : cancels exactly in training-mode BN
    const float* gamma = (const float*)d_in[3];
    const float* beta  = (const float*)d_in[4];
    float* out = (float*)d_out;

    cudaFuncSetAttribute(conv_tc, cudaFuncAttributeMaxDynamicSharedMemorySize, SMEM_REQ);
    conv_tc<<<148, 256, SMEM_REQ>>>(x, wgt);
    finalize_stats<<<1, 64>>>(gamma, beta);
    bn_sort_kernel<<<16384, 256>>>(out);
}

// round 8
// speedup vs baseline: 5.4011x; 1.0825x over previous
#include <cuda_runtime.h>
#include <cuda_fp16.h>
#include <cstdint>

#define HW 65536
#define M_PER_CH (16*HW)

__device__ float g_conv[(size_t)16*64*HW];     // 256 MB scratch
__device__ float g_psum[64*148];
__device__ float g_psq[64*148];
__device__ float g_scale[64];
__device__ float g_shift[64];

// SMEM layout (dynamic):
//   W tiles : [0, 82944)            9 taps x [64 co][72 halves] (stride 144B)
//   A ring  : [82944, +4*19008)     4 slots x [132 px][72 halves]
#define WOFF 0
#define AOFF 82944
#define ATILE 19008
#define SMEM_REQ (82944 + 4*19008)
#define WTAP 9216      // 64*144

__device__ __forceinline__ uint32_t s2u(const void* p) {
    uint32_t a;
    asm("{ .reg .u64 t; cvta.to.shared.u64 t, %1; cvt.u32.u64 %0, t; }" : "=r"(a) : "l"(p));
    return a;
}
__device__ __forceinline__ void ldsm4(uint32_t& r0, uint32_t& r1, uint32_t& r2, uint32_t& r3,
                                      uint32_t addr) {
    asm volatile("ldmatrix.sync.aligned.m8n8.x4.shared.b16 {%0,%1,%2,%3}, [%4];"
                 : "=r"(r0), "=r"(r1), "=r"(r2), "=r"(r3) : "r"(addr));
}
__device__ __forceinline__ void mma16816(float* c, uint32_t a0, uint32_t a1, uint32_t a2,
                                         uint32_t a3, uint32_t b0, uint32_t b1) {
    asm volatile("mma.sync.aligned.m16n8k16.row.col.f32.f16.f16.f32 "
                 "{%0,%1,%2,%3}, {%4,%5,%6,%7}, {%8,%9}, {%0,%1,%2,%3};"
                 : "+f"(c[0]), "+f"(c[1]), "+f"(c[2]), "+f"(c[3])
                 : "r"(a0), "r"(a1), "r"(a2), "r"(a3), "r"(b0), "r"(b1));
}
__device__ __forceinline__ uint32_t packh2(float a, float b) {
    __half2 h = __floats2half2_rn(a, b);
    return *(uint32_t*)&h;
}

// Load one x row (132 px x 64 ci) into regs
__device__ __forceinline__ void stage_load(const float* __restrict__ x, int n, int hrow,
                                           int w0, int t, uint4 pk[4], uint4& pke)
{
    const bool rowok = ((unsigned)hrow < 256u);
    const int px   = t & 127;
    const int octh = t >> 7;
    const int wg   = w0 - 2 + px;
    const bool wok = rowok && ((unsigned)wg < 256u);
    const size_t rb = (size_t)(hrow*256 + wg);

    #pragma unroll
    for (int r = 0; r < 4; r++) {
        const int oct = 2*r + octh;
        const size_t base = (((size_t)(n*64 + oct*8)) << 16) + rb;
        float v[8];
        #pragma unroll
        for (int i = 0; i < 8; i++)
            v[i] = wok ? __ldg(&x[base + ((size_t)i << 16)]) : 0.f;
        pk[r].x = packh2(v[0], v[1]);
        pk[r].y = packh2(v[2], v[3]);
        pk[r].z = packh2(v[4], v[5]);
        pk[r].w = packh2(v[6], v[7]);
    }
    pke = make_uint4(0, 0, 0, 0);
    if (t < 32) {
        const int pxe = 128 + (t & 3);
        const int oct = t >> 2;
        const int we = w0 - 2 + pxe;
        const bool ewok = rowok && ((unsigned)we < 256u);
        const size_t base = (((size_t)(n*64 + oct*8)) << 16) + (size_t)(hrow*256 + we);
        float v[8];
        #pragma unroll
        for (int i = 0; i < 8; i++)
            v[i] = ewok ? __ldg(&x[base + ((size_t)i << 16)]) : 0.f;
        pke.x = packh2(v[0], v[1]);
        pke.y = packh2(v[2], v[3]);
        pke.z = packh2(v[4], v[5]);
        pke.w = packh2(v[6], v[7]);
    }
}

__device__ __forceinline__ void stage_store(char* sm, int slot, int t,
                                            const uint4 pk[4], const uint4& pke)
{
    char* base = sm + AOFF + slot * ATILE;
    const int px = t & 127, octh = t >> 7;
    #pragma unroll
    for (int r = 0; r < 4; r++)
        *(uint4*)(base + px*144 + (2*r + octh)*16) = pk[r];
    if (t < 32)
        *(uint4*)(base + (128 + (t & 3))*144 + (t >> 2)*16) = pke;
}

// ---------------------------------------------------------------------------
// HMMA implicit-GEMM dilated conv + fused channel stats.
// Double-row iterations: warps 0-3 -> row h, warps 4-7 -> row h+2, each
// warp M=32 x N=64. 4-slot ring, 2 new rows staged per iteration.
// Fragments stored directly to g_conv (scalar stores, correct C layout).
// ---------------------------------------------------------------------------
__global__ __launch_bounds__(256, 1)
void conv_tc(const float* __restrict__ x, const float* __restrict__ wgt)
{
    extern __shared__ char sm[];
    __shared__ float sredS[8*64], sredQ[8*64];

    const int t  = threadIdx.x;
    const int L  = t & 31;
    const int wi = t >> 5;
    const int rsel = wi >> 2;            // 0: row h, 1: row h+2
    const int Pm   = (wi & 3) * 32;

    // ---- stage weights: [tap][co][ci] fp16, row stride 144B ----
    {
        const int co = t & 63;
        const int o0 = t >> 6;   // 0..3
        for (int r = 0; r < 2; r++) {
            const int oct = o0 + 4*r;
            for (int tap = 0; tap < 9; tap++) {
                float v[8];
                #pragma unroll
                for (int i = 0; i < 8; i++)
                    v[i] = __ldg(&wgt[co*576 + (oct*8 + i)*9 + tap]);
                uint4 p;
                p.x = packh2(v[0], v[1]); p.y = packh2(v[2], v[3]);
                p.z = packh2(v[4], v[5]); p.w = packh2(v[6], v[7]);
                *(uint4*)(sm + WOFF + tap*WTAP + co*144 + oct*16) = p;
            }
        }
    }

    const uint32_t Ab = s2u(sm + AOFF);
    const uint32_t Wb = s2u(sm + WOFF);

    uint32_t aoffm[2];
    #pragma unroll
    for (int mi = 0; mi < 2; mi++)
        aoffm[mi] = (uint32_t)((Pm + mi*16 + (L & 15)) * 144 + ((L >> 4) * 16));
    const uint32_t bconst0 = Wb + (uint32_t)((((L >> 3) & 3)*8 + (L & 7)) * 144);
    const uint32_t bconst1 = bconst0 + 32*144;

    float2 accS2[8], accQ2[8];
    #pragma unroll
    for (int i = 0; i < 8; i++) {
        accS2[i] = make_float2(0.f, 0.f);
        accQ2[i] = make_float2(0.f, 0.f);
    }

    // double-tile partition: 4096 units over 148 CTAs
    const int d0 = (blockIdx.x * 4096) / 148;
    const int d1 = ((blockIdx.x + 1) * 4096) / 148;

    uint4 pkA[4], pkeA, pkB[4], pkeB;
    int D = d0;

    __syncthreads();   // weights staged

    while (D < d1) {
        const int chain = D >> 6;
        int k2 = D & 63;
        const int n  = chain >> 2;
        const int wc = (chain >> 1) & 1;
        const int p  = chain & 1;
        const int w0 = wc << 7;
        const int seg_end = (((chain + 1) << 6) < d1) ? ((chain + 1) << 6) : d1;

        // prologue: rows j=2k2 (h-2), j=2k2+1 (h); prefetch j=2k2+2, 2k2+3
        stage_load(x, n, p + 4*k2 - 2, w0, t, pkA, pkeA);
        stage_store(sm, (2*k2) & 3, t, pkA, pkeA);
        stage_load(x, n, p + 4*k2,     w0, t, pkA, pkeA);
        stage_store(sm, (2*k2 + 1) & 3, t, pkA, pkeA);
        stage_load(x, n, p + 4*k2 + 2, w0, t, pkA, pkeA);
        stage_load(x, n, p + 4*k2 + 4, w0, t, pkB, pkeB);

        for (; D < seg_end; D++, k2++) {
            stage_store(sm, (2*k2 + 2) & 3, t, pkA, pkeA);
            stage_store(sm, (2*k2 + 3) & 3, t, pkB, pkeB);
            __syncthreads();

            // prefetch next 2 rows (hidden under the MMA loop)
            if (D + 1 < seg_end) {
                stage_load(x, n, p + 4*k2 + 6, w0, t, pkA, pkeA);
                stage_load(x, n, p + 4*k2 + 8, w0, t, pkB, pkeB);
            }

            float c[64];
            #pragma unroll
            for (int i = 0; i < 64; i++) c[i] = 0.f;

            #pragma unroll
            for (int kh = 0; kh < 3; kh++) {
                const int sl = (2*k2 + rsel + kh) & 3;
                const uint32_t abase = Ab + (uint32_t)sl * ATILE;
                #pragma unroll
                for (int kw = 0; kw < 3; kw++) {
                    const uint32_t boffb = (uint32_t)((kh*3 + kw)*WTAP);
                    #pragma unroll
                    for (int ks = 0; ks < 4; ks++) {
                        const uint32_t aoff = (uint32_t)(kw*288 + ks*32);
                        const uint32_t boff = boffb + (uint32_t)(ks*32);
                        uint32_t A0[4], A1[4], B0[8], B1[8];
                        ldsm4(A0[0], A0[1], A0[2], A0[3], abase + aoffm[0] + aoff);
                        ldsm4(A1[0], A1[1], A1[2], A1[3], abase + aoffm[1] + aoff);
                        ldsm4(B0[0], B0[1], B0[2], B0[3], bconst0 + boff);
                        ldsm4(B1[0], B1[1], B1[2], B1[3], bconst0 + boff + 16);
                        ldsm4(B0[4], B0[5], B0[6], B0[7], bconst1 + boff);
                        ldsm4(B1[4], B1[5], B1[6], B1[7], bconst1 + boff + 16);
                        #pragma unroll
                        for (int nj = 0; nj < 8; nj++) {
                            mma16816(&c[nj*4],      A0[0], A0[1], A0[2], A0[3], B0[nj], B1[nj]);
                            mma16816(&c[32 + nj*4], A1[0], A1[1], A1[2], A1[3], B0[nj], B1[nj]);
                        }
                    }
                }
            }
            __syncthreads();   // ldsm reads complete before slots are overwritten

            // ---- epilogue: fragments -> g_conv (correct m16n8 C layout) ----
            // thread L holds: (c0,c1)=(co,co+1)@px0, (c2,c3)=(co,co+1)@px0+8
            const int h_r = p + 4*k2 + 2*rsel;
            const int coB = 2*(L & 3);
            const int pxq = L >> 2;
            #pragma unroll
            for (int nj = 0; nj < 8; nj++) {
                const int co = nj*8 + coB;
                const size_t gb0 = (((size_t)(n*64 + co)) << 16) + (size_t)h_r*256 + w0;
                const size_t gb1 = gb0 + HW;   // co+1
                #pragma unroll
                for (int mi = 0; mi < 2; mi++) {
                    const float* cf = &c[mi*32 + nj*4];
                    const int px0 = Pm + mi*16 + pxq;
                    g_conv[gb0 + px0]     = cf[0];
                    g_conv[gb1 + px0]     = cf[1];
                    g_conv[gb0 + px0 + 8] = cf[2];
                    g_conv[gb1 + px0 + 8] = cf[3];
                    accS2[nj].x += cf[0] + cf[2];
                    accS2[nj].y += cf[1] + cf[3];
                    accQ2[nj].x += cf[0]*cf[0] + cf[2]*cf[2];
                    accQ2[nj].y += cf[1]*cf[1] + cf[3]*cf[3];
                }
            }
        }
    }

    // ---- stats reduction: butterfly over lanes sharing (L&3), then smem ----
    #pragma unroll
    for (int nj = 0; nj < 8; nj++) {
        #pragma unroll
        for (int off = 4; off < 32; off <<= 1) {
            accS2[nj].x += __shfl_xor_sync(0xffffffffu, accS2[nj].x, off);
            accS2[nj].y += __shfl_xor_sync(0xffffffffu, accS2[nj].y, off);
            accQ2[nj].x += __shfl_xor_sync(0xffffffffu, accQ2[nj].x, off);
            accQ2[nj].y += __shfl_xor_sync(0xffffffffu, accQ2[nj].y, off);
        }
    }
    if (L < 4) {
        #pragma unroll
        for (int nj = 0; nj < 8; nj++) {
            const int co = nj*8 + 2*L;
            sredS[wi*64 + co]     = accS2[nj].x;
            sredS[wi*64 + co + 1] = accS2[nj].y;
            sredQ[wi*64 + co]     = accQ2[nj].x;
            sredQ[wi*64 + co + 1] = accQ2[nj].y;
        }
    }
    __syncthreads();
    if (t < 64) {
        float s = 0.f, q = 0.f;
        #pragma unroll
        for (int w = 0; w < 8; w++) { s += sredS[w*64 + t]; q += sredQ[w*64 + t]; }
        g_psum[t*148 + blockIdx.x] = s;
        g_psq [t*148 + blockIdx.x] = q;
    }
}

// ---------------------------------------------------------------------------
__global__ void finalize_stats(const float* __restrict__ gamma,
                               const float* __restrict__ beta)
{
    int c = threadIdx.x;   // 64 threads
    float s = 0.f, q = 0.f;
    for (int b = 0; b < 148; b++) { s += g_psum[c*148 + b]; q += g_psq[c*148 + b]; }
    const float invM = 1.f / (float)M_PER_CH;
    float m   = s * invM;
    float var = q * invM - m*m;
    float inv = rsqrtf(var + 1e-5f);
    float sc  = gamma[c] * inv;
    g_scale[c] = sc;
    g_shift[c] = beta[c] - sc * m;
}

// ---------------------------------------------------------------------------
// normalize + ReLU + 4x4 block bitonic sort; write [a | y]  (DRAM roofline)
// ---------------------------------------------------------------------------
__global__ __launch_bounds__(256) void bn_sort_kernel(float* __restrict__ out)
{
    int tid = blockIdx.x * 256 + threadIdx.x;
    int bw = tid & 63, bh = (tid >> 6) & 63, c = (tid >> 12) & 63, n = tid >> 18;
    float sc = g_scale[c], sh = g_shift[c];

    size_t ibase = ((((size_t)(n*64 + c)) << 8) + bh*4) * 256 + bw*4;
    float v[16];
    #pragma unroll
    for (int r = 0; r < 4; r++) {
        float4 q = *(const float4*)&g_conv[ibase + (size_t)r*256];
        v[r*4+0] = fmaxf(fmaf(q.x, sc, sh), 0.f);
        v[r*4+1] = fmaxf(fmaf(q.y, sc, sh), 0.f);
        v[r*4+2] = fmaxf(fmaf(q.z, sc, sh), 0.f);
        v[r*4+3] = fmaxf(fmaf(q.w, sc, sh), 0.f);
    }
    size_t obase = ((((size_t)(n*128 + c)) << 8) + bh*4) * 256 + bw*4;
    #pragma unroll
    for (int r = 0; r < 4; r++)
        *(float4*)&out[obase + (size_t)r*256] =
            make_float4(v[r*4+0], v[r*4+1], v[r*4+2], v[r*4+3]);

    #pragma unroll
    for (int k = 2; k <= 16; k <<= 1)
        #pragma unroll
        for (int j = k >> 1; j > 0; j >>= 1)
            #pragma unroll
            for (int i = 0; i < 16; i++) {
                int ix = i ^ j;
                if (ix > i) {
                    float a = v[i], b = v[ix];
                    float lo = fminf(a, b), hi = fmaxf(a, b);
                    bool up = ((i & k) == 0);
                    v[i] = up ? lo : hi; v[ix] = up ? hi : lo;
                }
            }

    size_t ybase = obase + ((size_t)64 << 16);
    #pragma unroll
    for (int r = 0; r < 4; r++)
        *(float4*)&out[ybase + (size_t)r*256] =
            make_float4(v[r*4+0], v[r*4+1], v[r*4+2], v[r*4+3]);
}

// ---------------------------------------------------------------------------
extern "C" void kernel_launch(void* const* d_in, const int* in_sizes, int n_in,
                              void* d_out, int out_size)
{
    const float* x     = (const float*)d_in[0];
    const float* wgt   = (const float*)d_in[1];
    // d_in[2] = conv_b : cancels exactly in training-mode BN
    const float* gamma = (const float*)d_in[3];
    const float* beta  = (const float*)d_in[4];
    float* out = (float*)d_out;

    cudaFuncSetAttribute(conv_tc, cudaFuncAttributeMaxDynamicSharedMemorySize, SMEM_REQ);
    conv_tc<<<148, 256, SMEM_REQ>>>(x, wgt);
    finalize_stats<<<1, 64>>>(gamma, beta);
    bn_sort_kernel<<<16384, 256>>>(out);
}